// round 12
// baseline (speedup 1.0000x reference)
#include <cuda_runtime.h>
#include <cuda_fp16.h>
#include <cstdint>

#define HH 1024
#define WW 1024
#define XV 4      // output pixels per thread (one float4 store)
#define RWS 16    // output rows per thread strip

// One converted input row over the 8-float window v = cols x0-2 .. x0+5:
// A[m] = (v[2m], v[2m+1]) m=0..3 ; S[m] = (v[2m+1], v[2m+2]) m=0..2
struct RowH {
    __half2 A[4];
    __half2 S[3];
};

__device__ __forceinline__ void load_row(RowH& R, const float* __restrict__ ip,
                                         int y, int x0, bool interior) {
    float v[8];
    const float INFv = __int_as_float(0x7f800000);
    if (y < 0 || y >= HH) {
#pragma unroll
        for (int m = 0; m < 8; ++m) v[m] = INFv;
    } else if (interior) {
        const float* base = ip + (size_t)y * WW + x0;
        float2 p0 = *reinterpret_cast<const float2*>(base - 2);
        float4 p1 = *reinterpret_cast<const float4*>(base);
        float2 p2 = *reinterpret_cast<const float2*>(base + 4);
        v[0] = p0.x; v[1] = p0.y;
        v[2] = p1.x; v[3] = p1.y; v[4] = p1.z; v[5] = p1.w;
        v[6] = p2.x; v[7] = p2.y;
    } else {
        const float* base = ip + (size_t)y * WW;
#pragma unroll
        for (int m = 0; m < 8; ++m) {
            int col = x0 - 2 + m;
            v[m] = (col >= 0 && col < WW) ? base[col] : INFv;
        }
    }
#pragma unroll
    for (int m = 0; m < 4; ++m) R.A[m] = __floats2half2_rn(v[2 * m], v[2 * m + 1]);
#pragma unroll
    for (int m = 0; m < 3; ++m) R.S[m] = __floats2half2_rn(v[2 * m + 1], v[2 * m + 2]);
}

__global__ __launch_bounds__(128)
void erosion5x5_h2c4_kernel(const float* __restrict__ img,
                            const float* __restrict__ filt,
                            float* __restrict__ out) {
    const int x0 = (blockIdx.x * blockDim.x + threadIdx.x) * XV;
    const int y0 = blockIdx.y * RWS;
    const size_t plane = (size_t)blockIdx.z * (size_t)HH * (size_t)WW;
    const float* ip = img + plane;
    float* op = out + plane;

    const bool interior = (x0 >= 2) && (x0 + 6 <= WW);

    // Filter taps broadcast to half2 (L1-hot loads, hoisted by full unroll)
    __half2 hf[25];
#pragma unroll
    for (int t = 0; t < 25; ++t) hf[t] = __float2half2_rn(filt[t]);

    // Rolling 5-row ring: slot k%5 holds input row y0+k-2 (full unroll -> static)
    RowH W[5];
#pragma unroll
    for (int k = 0; k < 4; ++k)
        load_row(W[k], ip, y0 + k - 2, x0, interior);

#pragma unroll
    for (int r = 0; r < RWS; ++r) {
        load_row(W[(r + 4) % 5], ip, y0 + r + 2, x0, interior);

        // 4 independent chains: 2 packed accumulators x tap-parity split.
        // a0* covers pixels (0,1); a1* covers pixels (2,3). Even taps -> *e, odd -> *o.
        __half2 a0e, a0o, a1e, a1o;
        bool i0e = true, i0o = true;   // compile-time (full unroll) init flags
#pragma unroll
        for (int t = 0; t < 25; ++t) {
            const int i = t / 5;
            const int j = t % 5;
            const RowH& R = W[(r + i) % 5];
            const __half2 f = hf[t];
            // pixel pair (0,1) reads window cols (j, j+1); pair (2,3) reads (j+2, j+3)
            const __half2 p0 = ((j & 1) == 0) ? R.A[j / 2] : R.S[(j - 1) / 2];
            const __half2 p1 = ((j & 1) == 0) ? R.A[j / 2 + 1] : R.S[(j - 1) / 2 + 1];
            const __half2 s0 = __hsub2(p0, f);
            const __half2 s1 = __hsub2(p1, f);
            if ((t & 1) == 0) {
                if (i0e) { a0e = s0; a1e = s1; i0e = false; }
                else     { a0e = __hmin2(a0e, s0); a1e = __hmin2(a1e, s1); }
            } else {
                if (i0o) { a0o = s0; a1o = s1; i0o = false; }
                else     { a0o = __hmin2(a0o, s0); a1o = __hmin2(a1o, s1); }
            }
        }
        const __half2 a0 = __hmin2(a0e, a0o);
        const __half2 a1 = __hmin2(a1e, a1o);

        float2 lo = __half22float2(a0);
        float2 hi = __half22float2(a1);
        *reinterpret_cast<float4*>(op + (size_t)(y0 + r) * WW + x0) =
            make_float4(lo.x, lo.y, hi.x, hi.y);
    }
}

extern "C" void kernel_launch(void* const* d_in, const int* in_sizes, int n_in,
                              void* d_out, int out_size) {
    const float* image = (const float*)d_in[0];
    const float* filt  = (const float*)d_in[1];
    float* out = (float*)d_out;

    const int planes = in_sizes[0] / (HH * WW);  // 32*3 = 96

    dim3 block(128, 1, 1);
    dim3 grid(WW / (128 * XV), HH / RWS, planes);  // (2, 64, 96)
    erosion5x5_h2c4_kernel<<<grid, block>>>(image, filt, out);
}

// round 14
// speedup vs baseline: 1.0374x; 1.0374x over previous
#include <cuda_runtime.h>
#include <cstdint>

#define HH 1024
#define WW 1024
#define XV 4      // output pixels per thread in x (one float4)
#define RWS 16    // output rows per thread strip

__device__ __forceinline__ void loadrow(float* wr, const float* __restrict__ ip,
                                        int y, int x0, bool interior_x, float INFv) {
    if (y < 0 || y >= HH) {
#pragma unroll
        for (int c = 0; c < 12; ++c) wr[c] = INFv;
    } else if (interior_x) {
        const float4* p = reinterpret_cast<const float4*>(ip + (size_t)y * WW + (x0 - 4));
        float4 a = p[0], b = p[1], c4 = p[2];
        wr[0] = a.x;  wr[1] = a.y;  wr[2] = a.z;  wr[3] = a.w;
        wr[4] = b.x;  wr[5] = b.y;  wr[6] = b.z;  wr[7] = b.w;
        wr[8] = c4.x; wr[9] = c4.y; wr[10] = c4.z; wr[11] = c4.w;
    } else {
#pragma unroll
        for (int c = 0; c < 12; ++c) {
            int col = x0 - 4 + c;
            wr[c] = (col >= 0 && col < WW) ? ip[(size_t)y * WW + col] : INFv;
        }
    }
}

// Exact R1 body; ONLY change: min-blocks hint 9 -> reg cap 56 -> occ 50%->56%.
__global__ __launch_bounds__(128, 9)
void erosion5x5_occ9_kernel(const float* __restrict__ img,
                            const float* __restrict__ filt,
                            float* __restrict__ out) {
    const int x0 = (blockIdx.x * blockDim.x + threadIdx.x) * XV;
    const int y0 = blockIdx.y * RWS;
    const size_t plane = (size_t)blockIdx.z * (size_t)HH * (size_t)WW;
    const float* ip = img + plane;
    float* op = out + plane;

    // Filter into registers (L1-hot loads; ptxas may rematerialize under cap)
    float fv[25];
#pragma unroll
    for (int t = 0; t < 25; ++t) fv[t] = filt[t];

    const float INFv = __int_as_float(0x7f800000);
    const bool interior_x = (x0 >= 4) && (x0 + 8 <= WW);

    // Rolling raw window: slot k%5 holds input row y0+k-2.
    float w[5][12];
#pragma unroll
    for (int k = 0; k < 4; ++k)
        loadrow(w[k], ip, y0 + k - 2, x0, interior_x, INFv);

#pragma unroll
    for (int r = 0; r < RWS; ++r) {
        loadrow(w[(r + 4) % 5], ip, y0 + r + 2, x0, interior_x, INFv);

        float acc[XV];
        {
            const int s = r % 5;
            const float f0 = fv[0];
#pragma unroll
            for (int c = 0; c < XV; ++c) acc[c] = w[s][c + 2] - f0;
        }
#pragma unroll
        for (int i = 0; i < 5; ++i) {
            const int s = (r + i) % 5;  // input row y0+r+i-2
#pragma unroll
            for (int j = 0; j < 5; ++j) {
                if (i == 0 && j == 0) continue;
                const float f = fv[i * 5 + j];
#pragma unroll
                for (int c = 0; c < XV; ++c) {
                    // w index: (x0+c+j-2) - (x0-4) = c + j + 2
                    acc[c] = fminf(acc[c], w[s][c + j + 2] - f);
                }
            }
        }

        float4 o;
        o.x = acc[0]; o.y = acc[1]; o.z = acc[2]; o.w = acc[3];
        *reinterpret_cast<float4*>(op + (size_t)(y0 + r) * WW + x0) = o;
    }
}

extern "C" void kernel_launch(void* const* d_in, const int* in_sizes, int n_in,
                              void* d_out, int out_size) {
    const float* image = (const float*)d_in[0];
    const float* filt  = (const float*)d_in[1];
    float* out = (float*)d_out;

    const int planes = in_sizes[0] / (HH * WW);  // 32*3 = 96

    dim3 block(128, 1, 1);
    dim3 grid(WW / (128 * XV), HH / RWS, planes);  // (2, 64, 96)
    erosion5x5_occ9_kernel<<<grid, block>>>(image, filt, out);
}

// round 15
// speedup vs baseline: 1.0528x; 1.0148x over previous
#include <cuda_runtime.h>
#include <cstdint>

#define HH 1024
#define WW 1024
#define XV 2      // output pixels per thread in x (one float2 store)
#define RWS 16    // output rows per thread strip

// Window: input cols x0-2 .. x0+3 (6 floats) -> taps for pixels x0, x0+1.
__device__ __forceinline__ void loadrow6(float* wr, const float* __restrict__ ip,
                                         int y, int x0, bool interior_x, float INFv) {
    if (y < 0 || y >= HH) {
#pragma unroll
        for (int c = 0; c < 6; ++c) wr[c] = INFv;
    } else if (interior_x) {
        const float* base = ip + (size_t)y * WW + x0;   // x0 even -> 8B aligned
        float2 a = *reinterpret_cast<const float2*>(base - 2);
        float2 b = *reinterpret_cast<const float2*>(base);
        float2 c2 = *reinterpret_cast<const float2*>(base + 2);
        wr[0] = a.x;  wr[1] = a.y;
        wr[2] = b.x;  wr[3] = b.y;
        wr[4] = c2.x; wr[5] = c2.y;
    } else {
#pragma unroll
        for (int c = 0; c < 6; ++c) {
            int col = x0 - 2 + c;
            wr[c] = (col >= 0 && col < WW) ? ip[(size_t)y * WW + col] : INFv;
        }
    }
}

__global__ __launch_bounds__(128)
void erosion5x5_xv2_kernel(const float* __restrict__ img,
                           const float* __restrict__ filt,
                           float* __restrict__ out) {
    const int x0 = (blockIdx.x * blockDim.x + threadIdx.x) * XV;
    const int y0 = blockIdx.y * RWS;
    const size_t plane = (size_t)blockIdx.z * (size_t)HH * (size_t)WW;
    const float* ip = img + plane;
    float* op = out + plane;

    // Filter into registers (L1-hot loads, hoisted by full unroll) — as R1
    float fv[25];
#pragma unroll
    for (int t = 0; t < 25; ++t) fv[t] = filt[t];

    const float INFv = __int_as_float(0x7f800000);
    const bool interior_x = (x0 >= 2) && (x0 + 4 <= WW);

    // Rolling ring: slot k%5 holds input row y0+k-2 (full unroll -> static)
    float w[5][6];
#pragma unroll
    for (int k = 0; k < 4; ++k)
        loadrow6(w[k], ip, y0 + k - 2, x0, interior_x, INFv);

#pragma unroll
    for (int r = 0; r < RWS; ++r) {
        loadrow6(w[(r + 4) % 5], ip, y0 + r + 2, x0, interior_x, INFv);

        // R1 serial-chain body (proven best shape), 2 pixels wide.
        float acc[XV];
        {
            const int s = r % 5;
            const float f0 = fv[0];
#pragma unroll
            for (int c = 0; c < XV; ++c) acc[c] = w[s][c] - f0;
        }
#pragma unroll
        for (int i = 0; i < 5; ++i) {
            const int s = (r + i) % 5;  // input row y0+r+i-2
#pragma unroll
            for (int j = 0; j < 5; ++j) {
                if (i == 0 && j == 0) continue;
                const float f = fv[i * 5 + j];
#pragma unroll
                for (int c = 0; c < XV; ++c) {
                    // window index: (x0+c+j-2) - (x0-2) = c + j
                    acc[c] = fminf(acc[c], w[s][c + j] - f);
                }
            }
        }

        float2 o;
        o.x = acc[0]; o.y = acc[1];
        *reinterpret_cast<float2*>(op + (size_t)(y0 + r) * WW + x0) = o;
    }
}

extern "C" void kernel_launch(void* const* d_in, const int* in_sizes, int n_in,
                              void* d_out, int out_size) {
    const float* image = (const float*)d_in[0];
    const float* filt  = (const float*)d_in[1];
    float* out = (float*)d_out;

    const int planes = in_sizes[0] / (HH * WW);  // 32*3 = 96

    dim3 block(128, 1, 1);
    dim3 grid(WW / (128 * XV), HH / RWS, planes);  // (4, 64, 96)
    erosion5x5_xv2_kernel<<<grid, block>>>(image, filt, out);
}

// round 16
// speedup vs baseline: 1.2396x; 1.1774x over previous
#include <cuda_runtime.h>
#include <cstdint>

#define HH 1024
#define WW 1024
#define XV 4      // output pixels per thread in x (one float4)
#define RWS 16    // output rows per thread strip

__device__ __forceinline__ void loadrow(float* wr, const float* __restrict__ ip,
                                        int y, int x0, bool interior_x, float INFv) {
    if (y < 0 || y >= HH) {
#pragma unroll
        for (int c = 0; c < 12; ++c) wr[c] = INFv;
    } else if (interior_x) {
        const float4* p = reinterpret_cast<const float4*>(ip + (size_t)y * WW + (x0 - 4));
        float4 a = p[0], b = p[1], c4 = p[2];
        wr[0] = a.x;  wr[1] = a.y;  wr[2] = a.z;  wr[3] = a.w;
        wr[4] = b.x;  wr[5] = b.y;  wr[6] = b.z;  wr[7] = b.w;
        wr[8] = c4.x; wr[9] = c4.y; wr[10] = c4.z; wr[11] = c4.w;
    } else {
#pragma unroll
        for (int c = 0; c < 12; ++c) {
            int col = x0 - 4 + c;
            wr[c] = (col >= 0 && col < WW) ? ip[(size_t)y * WW + col] : INFv;
        }
    }
}

__global__ __launch_bounds__(128)
void erosion5x5_kernel(const float* __restrict__ img,
                       const float* __restrict__ filt,
                       float* __restrict__ out) {
    const int x0 = (blockIdx.x * blockDim.x + threadIdx.x) * XV;
    const int y0 = blockIdx.y * RWS;
    const size_t plane = (size_t)blockIdx.z * (size_t)HH * (size_t)WW;
    const float* ip = img + plane;
    float* op = out + plane;

    // Filter into registers (25 values, L1-hot loads, hoisted by full unroll)
    float fv[25];
#pragma unroll
    for (int t = 0; t < 25; ++t) fv[t] = filt[t];

    const float INFv = __int_as_float(0x7f800000);
    const bool interior_x = (x0 >= 4) && (x0 + 8 <= WW);

    // Rolling raw window: slot k%5 holds input row y0+k-2.
    float w[5][12];

    // Prologue: rows y0-2 .. y0+1 into slots 0..3
#pragma unroll
    for (int k = 0; k < 4; ++k)
        loadrow(w[k], ip, y0 + k - 2, x0, interior_x, INFv);

#pragma unroll
    for (int r = 0; r < RWS; ++r) {
        // Bring in input row y0+r+2 (slot (r+4)%5)
        loadrow(w[(r + 4) % 5], ip, y0 + r + 2, x0, interior_x, INFv);

        float acc[XV];
        // First tap (i=0,j=0): plain assignment, saves 4 mins
        {
            const int s = r % 5;
            const float f0 = fv[0];
#pragma unroll
            for (int c = 0; c < XV; ++c) acc[c] = w[s][c + 2] - f0;
        }
#pragma unroll
        for (int i = 0; i < 5; ++i) {
            const int s = (r + i) % 5;  // input row y0+r+i-2
#pragma unroll
            for (int j = 0; j < 5; ++j) {
                if (i == 0 && j == 0) continue;
                const float f = fv[i * 5 + j];
#pragma unroll
                for (int c = 0; c < XV; ++c) {
                    // w index: (x0+c+j-2) - (x0-4) = c + j + 2
                    acc[c] = fminf(acc[c], w[s][c + j + 2] - f);
                }
            }
        }

        float4 o;
        o.x = acc[0]; o.y = acc[1]; o.z = acc[2]; o.w = acc[3];
        *reinterpret_cast<float4*>(op + (size_t)(y0 + r) * WW + x0) = o;
    }
}

extern "C" void kernel_launch(void* const* d_in, const int* in_sizes, int n_in,
                              void* d_out, int out_size) {
    const float* image = (const float*)d_in[0];
    const float* filt  = (const float*)d_in[1];
    float* out = (float*)d_out;

    const int planes = in_sizes[0] / (HH * WW);  // 32*3 = 96

    dim3 block(128, 1, 1);
    dim3 grid(WW / (128 * XV), HH / RWS, planes);  // (2, 64, 96)
    erosion5x5_kernel<<<grid, block>>>(image, filt, out);
}